// round 11
// baseline (speedup 1.0000x reference)
#include <cuda_runtime.h>

// inputs: float32 [16, 64, 256, 256] NCHW
#define NB      16
#define NC      64
#define HW4     16384                 // float4 per (n,c) slice
#define SLICE4  (NC * HW4)
#define TPB     256
#define EPS     1e-5f

#define NR      8                     // rounds
#define CPR     8                     // channels per round
#define BPC     64                    // blocks per channel
#define NBLK    512                   // all co-resident (<= 148*4 slots)
#define HALF    8                     // float4 per thread per half-tile
#define TILE4   (HALF * TPB)          // 2048 float4 = 32 KB (stashed half)

__device__ float g_sum[NC];
__device__ float g_sq [NC];
__device__ float g_scale[NC];
__device__ float g_bias [NC];
__device__ int   g_done [NC];
__device__ int   g_ready[NC];

__global__ void init_kernel() {
    const int t = threadIdx.x;
    if (t < NC) {
        g_sum[t] = 0.0f; g_sq[t] = 0.0f;
        g_done[t] = 0;   g_ready[t] = 0;
    }
}

// Accumulate a float4 into (s, q)
__device__ __forceinline__ void acc4(const float4& v, float& s, float& q) {
    s += (v.x + v.y) + (v.z + v.w);
    q += (v.x * v.x + v.y * v.y) + (v.z * v.z + v.w * v.w);
}

// Block-reduce (s,q) and fold into channel c; last block publishes stats.
// Uses parity-selected smem arrays so no trailing barrier is needed.
__device__ __forceinline__ void fold_and_gate(
    float s, float q, int c, float* sh_s, float* sh_q,
    int tid, int lane, int wid)
{
    #pragma unroll
    for (int off = 16; off > 0; off >>= 1) {
        s += __shfl_down_sync(0xffffffffu, s, off);
        q += __shfl_down_sync(0xffffffffu, q, off);
    }
    if (lane == 0) { sh_s[wid] = s; sh_q[wid] = q; }
    __syncthreads();                       // the ONE barrier per round

    if (tid == 0) {
        float ss = sh_s[0], qq = sh_q[0];
        #pragma unroll
        for (int w = 1; w < 8; w++) { ss += sh_s[w]; qq += sh_q[w]; }
        atomicAdd(&g_sum[c], ss);
        atomicAdd(&g_sq [c], qq);
        __threadfence();
        const int old = atomicAdd(&g_done[c], 1);
        if (old == BPC - 1) {
            __threadfence();
            const float invN = 1.0f / (float)(NB * HW4 * 4);
            const float mean = g_sum[c] * invN;
            const float rstd = rsqrtf(g_sq[c] * invN - mean * mean + EPS);
            g_scale[c] = rstd;
            g_bias [c] = -mean * rstd;
            __threadfence();
            atomicExch(&g_ready[c], 1);
        }
    }
}

__global__ void __launch_bounds__(TPB, 4)
fused_kernel(const float4* __restrict__ in, float4* __restrict__ out) {
    const int tid  = threadIdx.x;
    const int lane = tid & 31;
    const int wid  = tid >> 5;

    // 64 blocks per channel; tile = quarter of one (n,c) slice (64 KB).
    const int cidx = blockIdx.x >> 6;          // channel within round [0,8)
    const int b    = blockIdx.x & 63;
    const int n    = b >> 2;
    const int hw0  = (b & 3) * 4096;

    __shared__ float  sh_s[2][8], sh_q[2][8];  // parity double-buffer
    __shared__ float4 buf[TILE4];              // 32 KB stash (A half)

    const size_t tbase = (size_t)n * SLICE4 + hw0 + tid;
    float4 v[HALF];

    // ── prologue: full reduce of round 0 ──
    {
        const size_t base = tbase + (size_t)cidx * HW4;
        float s = 0.0f, q = 0.0f;
        #pragma unroll
        for (int k = 0; k < HALF; k++) v[k] = __ldcg(&in[base + k * TPB]);      // A: L2 only
        #pragma unroll
        for (int k = 0; k < HALF; k++) { acc4(v[k], s, q); buf[k * TPB + tid] = v[k]; }
        #pragma unroll
        for (int k = 0; k < HALF; k++) v[k] = in[base + (HALF + k) * TPB];      // B: L1-allocating
        #pragma unroll
        for (int k = 0; k < HALF; k++) acc4(v[k], s, q);
        fold_and_gate(s, q, cidx, sh_s[0], sh_q[0], tid, lane, wid);
    }

    for (int g = 0; g < NR; g++) {
        const int    c    = g * CPR + cidx;
        const size_t base = tbase + (size_t)c * HW4;
        const size_t nbase = tbase + (size_t)((g + 1) * CPR + cidx) * HW4;

        // 1) issue next round's A loads (L2-only; in flight over the wait)
        if (g + 1 < NR) {
            #pragma unroll
            for (int k = 0; k < HALF; k++) v[k] = __ldcg(&in[nbase + k * TPB]);
        }

        // 2) per-warp stats wait: lane 0 spins, broadcast via shfl (no block barrier)
        float scale, bias;
        if (lane == 0) {
            while (*((volatile int*)&g_ready[c]) == 0) __nanosleep(32);
            __threadfence();
            scale = g_scale[c];
            bias  = g_bias [c];
        }
        scale = __shfl_sync(0xffffffffu, scale, 0);
        bias  = __shfl_sync(0xffffffffu, bias, 0);

        // 3) normalize round g: A from smem stash, B re-read (L1 hits)
        #pragma unroll
        for (int k = 0; k < HALF; k++) {
            float4 t = buf[k * TPB + tid];
            float4 o;
            o.x = fmaf(t.x, scale, bias);
            o.y = fmaf(t.y, scale, bias);
            o.z = fmaf(t.z, scale, bias);
            o.w = fmaf(t.w, scale, bias);
            __stcs(&out[base + k * TPB], o);
        }
        #pragma unroll
        for (int k = 0; k < HALF; k++) {
            float4 t = in[base + (HALF + k) * TPB];
            float4 o;
            o.x = fmaf(t.x, scale, bias);
            o.y = fmaf(t.y, scale, bias);
            o.z = fmaf(t.z, scale, bias);
            o.w = fmaf(t.w, scale, bias);
            __stcs(&out[base + (HALF + k) * TPB], o);
        }

        // 4) fold next round: acc A, stash A (thread-private slots — no barrier
        //    needed: each slot is read/written only by its own thread, and this
        //    thread finished reading buf in step 3), then load+acc B, gate.
        if (g + 1 < NR) {
            float s = 0.0f, q = 0.0f;
            #pragma unroll
            for (int k = 0; k < HALF; k++) { acc4(v[k], s, q); buf[k * TPB + tid] = v[k]; }
            #pragma unroll
            for (int k = 0; k < HALF; k++) v[k] = in[nbase + (HALF + k) * TPB];
            #pragma unroll
            for (int k = 0; k < HALF; k++) acc4(v[k], s, q);
            fold_and_gate(s, q, (g + 1) * CPR + cidx,
                          sh_s[(g + 1) & 1], sh_q[(g + 1) & 1], tid, lane, wid);
        }
    }
}

extern "C" void kernel_launch(void* const* d_in, const int* in_sizes, int n_in,
                              void* d_out, int out_size) {
    const float4* in  = (const float4*)d_in[0];
    float4*       out = (float4*)d_out;

    init_kernel<<<1, 64>>>();
    fused_kernel<<<NBLK, TPB>>>(in, out);
}

// round 12
// speedup vs baseline: 1.3047x; 1.3047x over previous
#include <cuda_runtime.h>

// inputs: float32 [16, 64, 256, 256] NCHW
#define NB      16
#define NC      64
#define HW4     16384                 // float4 per (n,c) slice
#define SLICE4  (NC * HW4)
#define TPB     256
#define EPS     1e-5f

#define NR      8                     // rounds (channel groups of 8)
#define CPR     8                     // channels per round
#define BPC     64                    // blocks per channel
#define NBLK    512                   // all co-resident (<= 148*4 slots)
#define ITERS   16                    // float4 per thread per tile (64 KB tile)

// Zero-initialized device state; kernel restores zeros before exiting, so no
// init launch is needed (graph replays see clean state each time).
__device__ float g_sum[NC];
__device__ float g_sq [NC];
__device__ float g_scale[NC];
__device__ float g_bias [NC];
__device__ int   g_done [NC];
__device__ int   g_ready[NC];
__device__ int   g_fin;

// Reduce one 64 KB tile of channel c; fold into per-channel sums; the last
// arriving block of the channel finalizes scale/bias and raises ready[c].
__device__ __forceinline__ void reduce_tile(
    const float4* __restrict__ in, size_t base, int c,
    float* sh_s, float* sh_q, int tid, int lane, int wid)
{
    float s = 0.0f, q = 0.0f;
    {
        float4 v[8];
        #pragma unroll
        for (int k = 0; k < 8; k++) v[k] = in[base + k * TPB];
        #pragma unroll
        for (int k = 0; k < 8; k++) {
            s += (v[k].x + v[k].y) + (v[k].z + v[k].w);
            q += (v[k].x * v[k].x + v[k].y * v[k].y)
               + (v[k].z * v[k].z + v[k].w * v[k].w);
        }
        #pragma unroll
        for (int k = 0; k < 8; k++) v[k] = in[base + (k + 8) * TPB];
        #pragma unroll
        for (int k = 0; k < 8; k++) {
            s += (v[k].x + v[k].y) + (v[k].z + v[k].w);
            q += (v[k].x * v[k].x + v[k].y * v[k].y)
               + (v[k].z * v[k].z + v[k].w * v[k].w);
        }
    }

    #pragma unroll
    for (int off = 16; off > 0; off >>= 1) {
        s += __shfl_down_sync(0xffffffffu, s, off);
        q += __shfl_down_sync(0xffffffffu, q, off);
    }
    if (lane == 0) { sh_s[wid] = s; sh_q[wid] = q; }
    __syncthreads();

    if (tid == 0) {
        float ss = sh_s[0], qq = sh_q[0];
        #pragma unroll
        for (int w = 1; w < 8; w++) { ss += sh_s[w]; qq += sh_q[w]; }
        atomicAdd(&g_sum[c], ss);
        atomicAdd(&g_sq [c], qq);
        __threadfence();
        const int old = atomicAdd(&g_done[c], 1);
        if (old == BPC - 1) {
            __threadfence();
            const float invN = 1.0f / (float)(NB * HW4 * 4);
            const float mean = g_sum[c] * invN;
            const float rstd = rsqrtf(g_sq[c] * invN - mean * mean + EPS);
            g_scale[c] = rstd;
            g_bias [c] = -mean * rstd;
            __threadfence();
            atomicExch(&g_ready[c], 1);
        }
    }
    __syncthreads();   // sh_s/sh_q safe for reuse
}

__global__ void __launch_bounds__(TPB, 4)
fused_kernel(const float4* __restrict__ in, float4* __restrict__ out) {
    const int tid  = threadIdx.x;
    const int lane = tid & 31;
    const int wid  = tid >> 5;

    // Block -> tile: 64 blocks per channel; tile = quarter of one (n,c) slice.
    const int cidx = blockIdx.x >> 6;          // channel within round [0,8)
    const int b    = blockIdx.x & 63;
    const int n    = b >> 2;
    const int hw0  = (b & 3) * 4096;

    __shared__ float sh_s[8], sh_q[8];
    __shared__ float sh_sb[2][2];              // parity double-buffer

    const size_t tbase = (size_t)n * SLICE4 + hw0 + tid;

    // ── pipeline fill: reduce round 0 ──
    reduce_tile(in, tbase + (size_t)cidx * HW4, cidx, sh_s, sh_q, tid, lane, wid);

    for (int g = 0; g < NR; g++) {
        const int c = g * CPR + cidx;
        const int p = g & 1;

        // ── reduce next round first (hides the ready-wait below) ──
        if (g + 1 < NR) {
            const int cn = (g + 1) * CPR + cidx;
            reduce_tile(in, tbase + (size_t)cn * HW4, cn, sh_s, sh_q, tid, lane, wid);
        }

        // ── wait for my channel's stats (usually already set) ──
        if (tid == 0) {
            while (*((volatile int*)&g_ready[c]) == 0) __nanosleep(32);
            __threadfence();
            sh_sb[p][0] = g_scale[c];
            sh_sb[p][1] = g_bias [c];
        }
        __syncthreads();
        const float scale = sh_sb[p][0];
        const float bias  = sh_sb[p][1];

        // ── normalize my round-g tile; __ldlu = last-use so the re-read
        //    evicts immediately, freeing L2 for round g+1's inserts ──
        const size_t base = tbase + (size_t)c * HW4;
        #pragma unroll
        for (int k = 0; k < ITERS; k++) {
            const size_t idx = base + k * TPB;
            float4 v = __ldlu(&in[idx]);
            float4 o;
            o.x = fmaf(v.x, scale, bias);
            o.y = fmaf(v.y, scale, bias);
            o.z = fmaf(v.z, scale, bias);
            o.w = fmaf(v.w, scale, bias);
            out[idx] = o;
        }
        // no trailing barrier: next round writes sh_sb[1-p]
    }

    // ── self-reset for the next graph replay: last block to finish clears
    //    all state. Every block increments g_fin only AFTER its final use of
    //    g_ready/g_scale/g_bias, so the reset cannot race with a consumer. ──
    __syncthreads();
    if (tid == 0) {
        __threadfence();
        const int old = atomicAdd(&g_fin, 1);
        if (old == NBLK - 1) {
            #pragma unroll
            for (int t = 0; t < NC; t++) {
                g_sum[t] = 0.0f; g_sq[t] = 0.0f;
                g_done[t] = 0;   g_ready[t] = 0;
            }
            g_fin = 0;
            __threadfence();
        }
    }
}

extern "C" void kernel_launch(void* const* d_in, const int* in_sizes, int n_in,
                              void* d_out, int out_size) {
    const float4* in  = (const float4*)d_in[0];
    float4*       out = (float4*)d_out;

    fused_kernel<<<NBLK, TPB>>>(in, out);
}

// round 13
// speedup vs baseline: 1.5032x; 1.1522x over previous
#include <cuda_runtime.h>

// inputs: float32 [16, 64, 256, 256] NCHW
#define NB      16
#define NC      64
#define HW4     16384                 // float4 per (n,c) slice
#define SLICE4  (NC * HW4)
#define TPB     256
#define EPS     1e-5f

#define NR      8                     // rounds (channel groups of 8)
#define CPR     8                     // channels per round
#define BPC     64                    // blocks per channel
#define NBLK    512                   // all co-resident (<= 148*4 slots)
#define ITERS   16                    // float4 per thread per tile (64 KB tile)

// Zero-initialized device state; the kernel restores zeros before exiting,
// so no init launch is needed (graph replays see clean state every time).
__device__ float g_sum[NC];
__device__ float g_sq [NC];
__device__ float g_scale[NC];         // rstd
__device__ float g_bias [NC];         // -mean*rstd
__device__ int   g_done [NC];         // per-channel reduce arrivals
__device__ int   g_ready[NC];         // per-channel stats published
__device__ int   g_fin;               // blocks fully done with flag reads

// Reduce one 64 KB tile of channel c; fold into per-channel sums; the last
// arriving block of the channel finalizes scale/bias and raises ready[c].
__device__ __forceinline__ void reduce_tile(
    const float4* __restrict__ in, size_t base, int c,
    float* sh_s, float* sh_q, int tid, int lane, int wid)
{
    float s = 0.0f, q = 0.0f;
    {
        float4 v[8];
        #pragma unroll
        for (int k = 0; k < 8; k++) v[k] = in[base + k * TPB];
        #pragma unroll
        for (int k = 0; k < 8; k++) {
            s += (v[k].x + v[k].y) + (v[k].z + v[k].w);
            q += (v[k].x * v[k].x + v[k].y * v[k].y)
               + (v[k].z * v[k].z + v[k].w * v[k].w);
        }
        #pragma unroll
        for (int k = 0; k < 8; k++) v[k] = in[base + (k + 8) * TPB];
        #pragma unroll
        for (int k = 0; k < 8; k++) {
            s += (v[k].x + v[k].y) + (v[k].z + v[k].w);
            q += (v[k].x * v[k].x + v[k].y * v[k].y)
               + (v[k].z * v[k].z + v[k].w * v[k].w);
        }
    }

    #pragma unroll
    for (int off = 16; off > 0; off >>= 1) {
        s += __shfl_down_sync(0xffffffffu, s, off);
        q += __shfl_down_sync(0xffffffffu, q, off);
    }
    if (lane == 0) { sh_s[wid] = s; sh_q[wid] = q; }
    __syncthreads();

    if (tid == 0) {
        float ss = sh_s[0], qq = sh_q[0];
        #pragma unroll
        for (int w = 1; w < 8; w++) { ss += sh_s[w]; qq += sh_q[w]; }
        atomicAdd(&g_sum[c], ss);
        atomicAdd(&g_sq [c], qq);
        __threadfence();
        const int old = atomicAdd(&g_done[c], 1);
        if (old == BPC - 1) {
            __threadfence();
            const float invN = 1.0f / (float)(NB * HW4 * 4);
            const float mean = g_sum[c] * invN;
            const float rstd = rsqrtf(g_sq[c] * invN - mean * mean + EPS);
            g_scale[c] = rstd;
            g_bias [c] = -mean * rstd;
            __threadfence();
            atomicExch(&g_ready[c], 1);
        }
    }
    __syncthreads();   // sh_s/sh_q safe for reuse
}

__global__ void __launch_bounds__(TPB, 4)
fused_kernel(const float4* __restrict__ in, float4* __restrict__ out) {
    const int tid  = threadIdx.x;
    const int lane = tid & 31;
    const int wid  = tid >> 5;

    // Block -> tile: 64 blocks per channel; tile = quarter of one (n,c) slice.
    const int cidx = blockIdx.x >> 6;          // channel within round [0,8)
    const int b    = blockIdx.x & 63;
    const int n    = b >> 2;
    const int hw0  = (b & 3) * 4096;

    __shared__ float sh_s[8], sh_q[8];
    __shared__ float sh_sb[2];

    const size_t tbase = (size_t)n * SLICE4 + hw0 + tid;

    // ── pipeline fill: reduce round 0 ──
    reduce_tile(in, tbase + (size_t)cidx * HW4, cidx, sh_s, sh_q, tid, lane, wid);

    for (int g = 0; g < NR; g++) {
        const int c = g * CPR + cidx;

        // ── reduce next round first (hides the ready-wait below) ──
        if (g + 1 < NR) {
            const int cn = (g + 1) * CPR + cidx;
            reduce_tile(in, tbase + (size_t)cn * HW4, cn, sh_s, sh_q, tid, lane, wid);
        }

        // ── wait for my channel's stats (usually already set) ──
        if (tid == 0) {
            while (*((volatile int*)&g_ready[c]) == 0) __nanosleep(32);
            __threadfence();
            sh_sb[0] = g_scale[c];
            sh_sb[1] = g_bias [c];
        }
        __syncthreads();
        const float scale = sh_sb[0];
        const float bias  = sh_sb[1];

        // ── normalize my round-g tile (reads L2/L1-resident) ──
        const size_t base = tbase + (size_t)c * HW4;
        #pragma unroll
        for (int k = 0; k < ITERS; k++) {
            const size_t idx = base + k * TPB;
            float4 v = in[idx];
            float4 o;
            o.x = fmaf(v.x, scale, bias);
            o.y = fmaf(v.y, scale, bias);
            o.z = fmaf(v.z, scale, bias);
            o.w = fmaf(v.w, scale, bias);
            out[idx] = o;
        }
        __syncthreads();   // keep warps phase-locked (sh_sb reuse next round)
    }

    // ── self-reset for the next graph replay: last-finishing block clears
    //    all state. g_fin increments only AFTER this block's final use of
    //    g_ready/g_scale/g_bias, so the reset cannot race a consumer. ──
    if (tid == 0) {
        __threadfence();
        const int old = atomicAdd(&g_fin, 1);
        if (old == NBLK - 1) {
            #pragma unroll
            for (int t = 0; t < NC; t++) {
                g_sum[t] = 0.0f; g_sq[t] = 0.0f;
                g_done[t] = 0;   g_ready[t] = 0;
            }
            g_fin = 0;
            __threadfence();
        }
    }
}

extern "C" void kernel_launch(void* const* d_in, const int* in_sizes, int n_in,
                              void* d_out, int out_size) {
    const float4* in  = (const float4*)d_in[0];
    float4*       out = (float4*)d_out;

    fused_kernel<<<NBLK, TPB>>>(in, out);
}

// round 14
// speedup vs baseline: 1.5078x; 1.0031x over previous
#include <cuda_runtime.h>

// inputs: float32 [16, 64, 256, 256] NCHW
#define NB      16
#define NC      64
#define HW4     16384                 // float4 per (n,c) slice
#define SLICE4  (NC * HW4)
#define TPB     512
#define NWARP   (TPB / 32)            // 16
#define EPS     1e-5f

#define NR      8                     // rounds (channel groups of 8)
#define CPR     8                     // channels per round
#define BPC     64                    // blocks per channel
#define NBLK    512                   // all co-resident (148 SMs * 4 slots)
#define ITERS   8                     // float4 per thread per tile (64 KB tile)

// Zero-initialized device state; kernel restores zeros before exiting.
__device__ float g_sum[NC];
__device__ float g_sq [NC];
__device__ float g_scale[NC];
__device__ float g_bias [NC];
__device__ int   g_done [NC];
__device__ int   g_ready[NC];
__device__ int   g_fin;

// Reduce one 64 KB tile (4096 f4, 8 per thread) of channel c.
__device__ __forceinline__ void reduce_tile(
    const float4* __restrict__ in, size_t base, int c,
    float* sh_s, float* sh_q, int tid, int lane, int wid)
{
    float s = 0.0f, q = 0.0f;
    {
        float4 v[4];
        #pragma unroll
        for (int k = 0; k < 4; k++) v[k] = in[base + k * TPB];
        #pragma unroll
        for (int k = 0; k < 4; k++) {
            s += (v[k].x + v[k].y) + (v[k].z + v[k].w);
            q += (v[k].x * v[k].x + v[k].y * v[k].y)
               + (v[k].z * v[k].z + v[k].w * v[k].w);
        }
        #pragma unroll
        for (int k = 0; k < 4; k++) v[k] = in[base + (k + 4) * TPB];
        #pragma unroll
        for (int k = 0; k < 4; k++) {
            s += (v[k].x + v[k].y) + (v[k].z + v[k].w);
            q += (v[k].x * v[k].x + v[k].y * v[k].y)
               + (v[k].z * v[k].z + v[k].w * v[k].w);
        }
    }

    #pragma unroll
    for (int off = 16; off > 0; off >>= 1) {
        s += __shfl_down_sync(0xffffffffu, s, off);
        q += __shfl_down_sync(0xffffffffu, q, off);
    }
    if (lane == 0) { sh_s[wid] = s; sh_q[wid] = q; }
    __syncthreads();

    if (wid == 0) {
        s = (lane < NWARP) ? sh_s[lane] : 0.0f;
        q = (lane < NWARP) ? sh_q[lane] : 0.0f;
        #pragma unroll
        for (int off = 8; off > 0; off >>= 1) {
            s += __shfl_down_sync(0xffffffffu, s, off);
            q += __shfl_down_sync(0xffffffffu, q, off);
        }
        if (lane == 0) {
            atomicAdd(&g_sum[c], s);
            atomicAdd(&g_sq [c], q);
            __threadfence();
            const int old = atomicAdd(&g_done[c], 1);
            if (old == BPC - 1) {
                __threadfence();
                const float invN = 1.0f / (float)(NB * HW4 * 4);
                const float mean = g_sum[c] * invN;
                const float rstd = rsqrtf(g_sq[c] * invN - mean * mean + EPS);
                g_scale[c] = rstd;
                g_bias [c] = -mean * rstd;
                __threadfence();
                atomicExch(&g_ready[c], 1);
            }
        }
    }
    __syncthreads();   // sh_s/sh_q safe for reuse
}

__global__ void __launch_bounds__(TPB, 4)
fused_kernel(const float4* __restrict__ in, float4* __restrict__ out) {
    const int tid  = threadIdx.x;
    const int lane = tid & 31;
    const int wid  = tid >> 5;

    // 64 blocks per channel; tile = quarter of one (n,c) slice (64 KB).
    const int cidx = blockIdx.x >> 6;          // channel within round [0,8)
    const int b    = blockIdx.x & 63;
    const int n    = b >> 2;
    const int hw0  = (b & 3) * 4096;

    __shared__ float sh_s[NWARP], sh_q[NWARP];
    __shared__ float sh_sb[2];

    const size_t tbase = (size_t)n * SLICE4 + hw0 + tid;

    // ── pipeline fill: reduce round 0 ──
    reduce_tile(in, tbase + (size_t)cidx * HW4, cidx, sh_s, sh_q, tid, lane, wid);

    for (int g = 0; g < NR; g++) {
        const int c = g * CPR + cidx;

        // ── reduce next round first (hides the ready-wait below) ──
        if (g + 1 < NR) {
            const int cn = (g + 1) * CPR + cidx;
            reduce_tile(in, tbase + (size_t)cn * HW4, cn, sh_s, sh_q, tid, lane, wid);
        }

        // ── wait for my channel's stats (usually already set) ──
        if (tid == 0) {
            while (*((volatile int*)&g_ready[c]) == 0) __nanosleep(32);
            __threadfence();
            sh_sb[0] = g_scale[c];
            sh_sb[1] = g_bias [c];
        }
        __syncthreads();
        const float scale = sh_sb[0];
        const float bias  = sh_sb[1];

        // ── normalize my round-g tile ──
        const size_t base = tbase + (size_t)c * HW4;
        #pragma unroll
        for (int k = 0; k < ITERS; k++) {
            const size_t idx = base + k * TPB;
            float4 v = in[idx];
            float4 o;
            o.x = fmaf(v.x, scale, bias);
            o.y = fmaf(v.y, scale, bias);
            o.z = fmaf(v.z, scale, bias);
            o.w = fmaf(v.w, scale, bias);
            out[idx] = o;
        }
        __syncthreads();   // keep warps phase-locked (sh_sb reuse next round)
    }

    // ── self-reset for next graph replay (after final flag use) ──
    if (tid == 0) {
        __threadfence();
        const int old = atomicAdd(&g_fin, 1);
        if (old == NBLK - 1) {
            #pragma unroll
            for (int t = 0; t < NC; t++) {
                g_sum[t] = 0.0f; g_sq[t] = 0.0f;
                g_done[t] = 0;   g_ready[t] = 0;
            }
            g_fin = 0;
            __threadfence();
        }
    }
}

extern "C" void kernel_launch(void* const* d_in, const int* in_sizes, int n_in,
                              void* d_out, int out_size) {
    const float4* in  = (const float4*)d_in[0];
    float4*       out = (float4*)d_out;

    fused_kernel<<<NBLK, TPB>>>(in, out);
}

// round 15
// speedup vs baseline: 1.5858x; 1.0517x over previous
#include <cuda_runtime.h>

// inputs: float32 [16, 64, 256, 256] NCHW
#define NB      16
#define NC      64
#define HW4     16384                 // float4 per (n,c) slice
#define SLICE4  (NC * HW4)
#define TPB     512
#define NWARP   (TPB / 32)            // 16
#define EPS     1e-5f

#define NR      8                     // rounds (channel groups of 8)
#define CPR     8                     // channels per round
#define BPC     64                    // blocks per channel
#define NBLK    512                   // all co-resident (148 SMs * 4 slots)
#define ITERS   8                     // float4 per thread per tile (64 KB tile)
#define STASH   2                     // float4 per thread stashed in smem

// Zero-initialized device state; kernel restores zeros before exiting.
__device__ float g_sum[NC];
__device__ float g_sq [NC];
__device__ float g_scale[NC];
__device__ float g_bias [NC];
__device__ int   g_done [NC];
__device__ int   g_ready[NC];
__device__ int   g_fin;

// Reduce one 64 KB tile (8 f4/thread) of channel c; stash first STASH f4
// into buf (thread-private slots, no sync needed).
__device__ __forceinline__ void reduce_tile(
    const float4* __restrict__ in, size_t base, int c, float4* buf,
    float* sh_s, float* sh_q, int tid, int lane, int wid)
{
    float s = 0.0f, q = 0.0f;
    {
        float4 v[4];
        #pragma unroll
        for (int k = 0; k < 4; k++) v[k] = in[base + k * TPB];
        #pragma unroll
        for (int k = 0; k < STASH; k++) buf[k * TPB + tid] = v[k];
        #pragma unroll
        for (int k = 0; k < 4; k++) {
            s += (v[k].x + v[k].y) + (v[k].z + v[k].w);
            q += (v[k].x * v[k].x + v[k].y * v[k].y)
               + (v[k].z * v[k].z + v[k].w * v[k].w);
        }
        #pragma unroll
        for (int k = 0; k < 4; k++) v[k] = in[base + (k + 4) * TPB];
        #pragma unroll
        for (int k = 0; k < 4; k++) {
            s += (v[k].x + v[k].y) + (v[k].z + v[k].w);
            q += (v[k].x * v[k].x + v[k].y * v[k].y)
               + (v[k].z * v[k].z + v[k].w * v[k].w);
        }
    }

    #pragma unroll
    for (int off = 16; off > 0; off >>= 1) {
        s += __shfl_down_sync(0xffffffffu, s, off);
        q += __shfl_down_sync(0xffffffffu, q, off);
    }
    if (lane == 0) { sh_s[wid] = s; sh_q[wid] = q; }
    __syncthreads();

    if (wid == 0) {
        s = (lane < NWARP) ? sh_s[lane] : 0.0f;
        q = (lane < NWARP) ? sh_q[lane] : 0.0f;
        #pragma unroll
        for (int off = 8; off > 0; off >>= 1) {
            s += __shfl_down_sync(0xffffffffu, s, off);
            q += __shfl_down_sync(0xffffffffu, q, off);
        }
        if (lane == 0) {
            atomicAdd(&g_sum[c], s);
            atomicAdd(&g_sq [c], q);
            __threadfence();
            const int old = atomicAdd(&g_done[c], 1);
            if (old == BPC - 1) {
                __threadfence();
                const float invN = 1.0f / (float)(NB * HW4 * 4);
                const float mean = g_sum[c] * invN;
                const float rstd = rsqrtf(g_sq[c] * invN - mean * mean + EPS);
                g_scale[c] = rstd;
                g_bias [c] = -mean * rstd;
                __threadfence();
                atomicExch(&g_ready[c], 1);
            }
        }
    }
    __syncthreads();   // sh_s/sh_q safe for reuse
}

__global__ void __launch_bounds__(TPB, 4)
fused_kernel(const float4* __restrict__ in, float4* __restrict__ out) {
    const int tid  = threadIdx.x;
    const int lane = tid & 31;
    const int wid  = tid >> 5;

    // 64 blocks per channel; tile = quarter of one (n,c) slice (64 KB).
    const int cidx = blockIdx.x >> 6;          // channel within round [0,8)
    const int b    = blockIdx.x & 63;
    const int n    = b >> 2;
    const int hw0  = (b & 3) * 4096;

    __shared__ float  sh_s[NWARP], sh_q[NWARP];
    __shared__ float  sh_sb[2];
    __shared__ float4 buf[2][STASH * TPB];     // 2 x 16 KB parity stash

    const size_t tbase = (size_t)n * SLICE4 + hw0 + tid;

    // ── pipeline fill: reduce round 0 (stash -> buf[0]) ──
    reduce_tile(in, tbase + (size_t)cidx * HW4, cidx, buf[0],
                sh_s, sh_q, tid, lane, wid);

    for (int g = 0; g < NR; g++) {
        const int c = g * CPR + cidx;

        // ── reduce next round first (stash -> buf[(g+1)&1]; hides the wait) ──
        if (g + 1 < NR) {
            const int cn = (g + 1) * CPR + cidx;
            reduce_tile(in, tbase + (size_t)cn * HW4, cn, buf[(g + 1) & 1],
                        sh_s, sh_q, tid, lane, wid);
        }

        // ── wait for my channel's stats (usually already set) ──
        if (tid == 0) {
            while (*((volatile int*)&g_ready[c]) == 0) __nanosleep(32);
            __threadfence();
            sh_sb[0] = g_scale[c];
            sh_sb[1] = g_bias [c];
        }
        __syncthreads();
        const float scale = sh_sb[0];
        const float bias  = sh_sb[1];

        // ── normalize round g: first STASH f4 from smem, rest from global ──
        const size_t base = tbase + (size_t)c * HW4;
        const float4* myb = buf[g & 1];
        #pragma unroll
        for (int k = 0; k < STASH; k++) {
            float4 v = myb[k * TPB + tid];
            float4 o;
            o.x = fmaf(v.x, scale, bias);
            o.y = fmaf(v.y, scale, bias);
            o.z = fmaf(v.z, scale, bias);
            o.w = fmaf(v.w, scale, bias);
            out[base + k * TPB] = o;
        }
        #pragma unroll
        for (int k = STASH; k < ITERS; k++) {
            const size_t idx = base + k * TPB;
            float4 v = in[idx];
            float4 o;
            o.x = fmaf(v.x, scale, bias);
            o.y = fmaf(v.y, scale, bias);
            o.z = fmaf(v.z, scale, bias);
            o.w = fmaf(v.w, scale, bias);
            out[idx] = o;
        }
        __syncthreads();   // keep warps phase-locked (sh_sb reuse next round)
    }

    // ── self-reset for next graph replay (after final flag use) ──
    if (tid == 0) {
        __threadfence();
        const int old = atomicAdd(&g_fin, 1);
        if (old == NBLK - 1) {
            #pragma unroll
            for (int t = 0; t < NC; t++) {
                g_sum[t] = 0.0f; g_sq[t] = 0.0f;
                g_done[t] = 0;   g_ready[t] = 0;
            }
            g_fin = 0;
            __threadfence();
        }
    }
}

extern "C" void kernel_launch(void* const* d_in, const int* in_sizes, int n_in,
                              void* d_out, int out_size) {
    const float4* in  = (const float4*)d_in[0];
    float4*       out = (float4*)d_out;

    fused_kernel<<<NBLK, TPB>>>(in, out);
}